// round 5
// baseline (speedup 1.0000x reference)
#include <cuda_runtime.h>
#include <math.h>

#define S2 256
#define NB 8
#define NM 24
#define RP 257   // padded row pitch (floats) to dodge smem bank conflicts

__device__ float  g_hA[NB*33*S2*S2];
__device__ float  g_hB[NB*33*S2*S2];
__device__ float2 g_A [NB*33*S2*NM];
__device__ float2 g_Xf[NB*33*NM*NM];
__device__ float2 g_Yf[NB*32*NM*NM];
__device__ float2 g_Bf[NB*32*NM*S2];

__device__ __forceinline__ float gelu_exact(float v){
    return 0.5f*v*(1.0f + erff(v*0.7071067811865475f));
}

// packed dual-FMA: (a.x*b.x+c.x, a.y*b.y+c.y) in one FFMA2
__device__ __forceinline__ float2 ffma2(float2 a, float2 b, float2 c){
    float2 d;
    unsigned long long ra = *reinterpret_cast<unsigned long long*>(&a);
    unsigned long long rb = *reinterpret_cast<unsigned long long*>(&b);
    unsigned long long rc = *reinterpret_cast<unsigned long long*>(&c);
    unsigned long long rd;
    asm("fma.rn.f32x2 %0, %1, %2, %3;" : "=l"(rd) : "l"(ra), "l"(rb), "l"(rc));
    *reinterpret_cast<unsigned long long*>(&d) = rd;
    return d;
}

// row DFT from smem rowbuf -> g_A ; C channels, one (b,x) row per block, 256 thr
__device__ __forceinline__ void row_dft_emit(const float* rowbuf, const float2* tw,
                                             int C, int Cin, int b, int x, int tid){
    for (int i = tid; i < C*NM; i += 256){
        int c = i / NM, kyi = i - c*NM;
        int k = (kyi < 12) ? kyi : kyi + 105;
        const float* rp = rowbuf + c*RP;
        float re = 0.0f, im = 0.0f;
        int idx = 0;
#pragma unroll 4
        for (int y = 0; y < 256; y++){
            float2 wv = tw[idx & 255];
            float h = rp[y];
            re += h*wv.x;
            im -= h*wv.y;
            idx += k;
        }
        g_A[(((long)(b*Cin + c))*S2 + x)*NM + kyi] = make_float2(re, im);
    }
}

// ------- front: fc0 + grid feats + concat a + h*a (NCHW, 33 ch) + fused y-DFT ----
__global__ void __launch_bounds__(256) k_front(const float* __restrict__ x,
                        const float* __restrict__ ap,
                        const float* __restrict__ fw, const float* __restrict__ fb){
    __shared__ __align__(8) float ws[12*32];
    __shared__ __align__(8) float bs[32];
    __shared__ float2 tw[256];
    __shared__ float rowbuf[33*RP];
    int tid = threadIdx.x;
    for (int i = tid; i < 384; i += 256) ws[i] = fw[i];
    if (tid < 32) bs[tid] = fb[tid];
    {
        float s,c; sincosf(6.2831853071795864769f*(float)tid/256.0f, &s, &c);
        tw[tid] = make_float2(c, s);
    }
    __syncthreads();
    int xi = blockIdx.x, b = blockIdx.y;
    int y = tid;
    int pix = (b*S2 + xi)*S2 + y;
    const float* xp = x + (long)pix*10;
    float2 featp[12];
#pragma unroll
    for (int t=0;t<10;t++){ float f = xp[t]; featp[t] = make_float2(f,f); }
    { float f = xi*(1.0f/255.0f); featp[10] = make_float2(f,f); }
    { float f = y *(1.0f/255.0f); featp[11] = make_float2(f,f); }
    float av = ap[pix];
    float2 accp[16];
#pragma unroll
    for (int cc=0; cc<16; cc++) accp[cc] = *(const float2*)&bs[2*cc];
#pragma unroll
    for (int t=0; t<12; t++){
#pragma unroll
        for (int cc=0; cc<16; cc++)
            accp[cc] = ffma2(featp[t], *(const float2*)&ws[t*32 + 2*cc], accp[cc]);
    }
    int base = ((b*33)*S2 + xi)*S2 + y;
#pragma unroll
    for (int cc=0; cc<16; cc++){
        float v0 = accp[cc].x*av, v1 = accp[cc].y*av;
        g_hA[base + (2*cc  )*S2*S2] = v0;
        g_hA[base + (2*cc+1)*S2*S2] = v1;
        rowbuf[(2*cc  )*RP + y] = v0;
        rowbuf[(2*cc+1)*RP + y] = v1;
    }
    float a2 = av*av;
    g_hA[base + 32*S2*S2] = a2;
    rowbuf[32*RP + y] = a2;
    __syncthreads();
    row_dft_emit(rowbuf, tw, 33, 33, b, xi, tid);
}

// ---------------- forward DFT along x at 24 modes (complex) ----------------
__global__ void k_dftx(){
    __shared__ float2 twx[256];   // (cos, cos)
    __shared__ float2 twy[256];   // (sin, sin)
    __shared__ float2 As[64*NM];
    int tid = threadIdx.x; // 576 threads
    if (tid < 256){
        float s,c; sincosf(6.2831853071795864769f*(float)tid/256.0f, &s, &c);
        twx[tid] = make_float2(c, c);
        twy[tid] = make_float2(s, s);
    }
    int bc = blockIdx.x;
    int kx = tid / NM, ky = tid % NM;
    int kv = (kx < 12) ? kx : kx + 232;
    float2 acc1 = make_float2(0.f,0.f), acc2 = make_float2(0.f,0.f);
    for (int ch = 0; ch < 4; ch++){
        __syncthreads();
        for (int i = tid; i < 64*NM; i += 576)
            As[i] = g_A[((long)bc*S2 + ch*64)*NM + i];
        __syncthreads();
#pragma unroll 4
        for (int xr = 0; xr < 64; xr++){
            int xx = ch*64 + xr;
            float2 av = As[xr*NM + ky];
            int ti = (kv*xx)&255;
            acc1 = ffma2(av, twx[ti], acc1);
            acc2 = ffma2(av, twy[ti], acc2);
        }
    }
    // re = sum ax*c + ay*s ; im = sum ay*c - ax*s
    g_Xf[(long)bc*NM*NM + tid] = make_float2(acc1.x + acc2.y, acc1.y - acc2.x);
}

// ------- spectral multiply: one block per mode site, all 8 batches ----------
// weights read directly from rbw (layout [corner][c][o][m1][m2][2]); neighboring
// ky sites share 32B sectors, so unique DRAM traffic = tensor size (L2-served).
__global__ void __launch_bounds__(256) k_smul2(const float* __restrict__ rbw, int Cin){
    extern __shared__ float2 sh[];         // Ws[Cin*32] then Xs[8*Cin]
    float2* Ws = sh;
    float2* Xs = sh + Cin*32;
    int site = blockIdx.x;                 // 0..575 = kx*24+ky
    int kx = site / NM, ky = site % NM;
    int corner = (kx >= 12 ? 1 : 0) + (ky >= 12 ? 2 : 0);
    int m1 = (kx >= 12) ? kx - 12 : kx;
    int m2 = (ky >= 12) ? ky - 12 : ky;
    const float* wbase = rbw + ((long)corner*Cin*32*144 + m1*12 + m2)*2;
    int tid = threadIdx.x;
    for (int i = tid; i < Cin*32; i += 256){
        const float* p = wbase + (long)i*288;   // i = c*32 + o
        Ws[i] = make_float2(p[0], p[1]);
    }
    for (int i = tid; i < NB*Cin; i += 256){
        int b = i / Cin, c = i % Cin;
        Xs[i] = g_Xf[((long)(b*Cin + c))*NM*NM + site];
    }
    __syncthreads();
    int b = tid >> 5, o = tid & 31;
    float yr = 0.0f, yi = 0.0f;
    const float2* xrow = Xs + b*Cin;
    for (int c = 0; c < Cin; c++){
        float2 xv = xrow[c];
        float2 wv = Ws[c*32 + o];
        yr += xv.x*wv.x - xv.y*wv.y;
        yi += xv.x*wv.y + xv.y*wv.x;
    }
    g_Yf[((long)(b*32 + o))*NM*NM + site] = make_float2(yr, yi);
}

// ------- inverse DFT along x (24 modes -> 256), alpha/N^2 folded ------
__global__ void k_invx(){
    __shared__ float2 twx[256];   // (cos, cos)
    __shared__ float2 twy[256];   // (sin, sin)
    __shared__ float2 Ys[NM*NM];
    int tid = threadIdx.x;
    int o = blockIdx.x, b = blockIdx.y;
    {
        float s,c; sincosf(6.2831853071795864769f*(float)tid/256.0f, &s, &c);
        twx[tid] = make_float2(c, c);
        twy[tid] = make_float2(s, s);
    }
    for (int i = tid; i < NM*NM; i += 256)
        Ys[i] = g_Yf[((long)b*32 + o)*NM*NM + i];
    __syncthreads();
    int x = tid;
    for (int kyi = 0; kyi < NM; kyi++){
        float2 acc1 = make_float2(0.f,0.f), acc2 = make_float2(0.f,0.f);
#pragma unroll
        for (int kxi = 0; kxi < NM; kxi++){
            int kv = (kxi < 12) ? kxi : kxi + 232;
            float2 yv = Ys[kxi*NM + kyi];
            int ti = (kv*x)&255;
            acc1 = ffma2(yv, twx[ti], acc1);
            acc2 = ffma2(yv, twy[ti], acc2);
        }
        // re = yx*c - yy*s ; im = yx*s + yy*c
        float re = acc1.x - acc2.y;
        float im = acc2.x + acc1.y;
        int kyv = (kyi < 12) ? kyi : kyi + 105;
        float sc = (kyv == 0 || kyv == 128) ? (1.0f/65536.0f) : (2.0f/65536.0f);
        g_Bf[(((long)b*32 + o)*NM + kyi)*S2 + x] = make_float2(re*sc, im*sc);
    }
}

// ------- fused: inv-y DFT (Re) + 1x1 conv + bias + gelu + next-layer y-DFT -------
template<int CIN>
__global__ void __launch_bounds__(256) k_fuse(int flip, const float* __restrict__ cw,
                                              const float* __restrict__ cb, int last){
    const float* hin  = flip ? g_hB : g_hA;
    float*       hout = flip ? g_hA : g_hB;
    constexpr int CP = (CIN + 1) & ~1;      // padded channel pitch (even)
    constexpr int NPAIR = CP/2;
    __shared__ float2 tw[256];
    __shared__ __align__(8) float Bsx[32*NM];
    __shared__ __align__(8) float Bsy[32*NM];
    __shared__ __align__(8) float cws[32*CP];
    __shared__ float  cbs[32];
    __shared__ float  rowbuf[32*RP];
    int tid = threadIdx.x;
    int x = blockIdx.x, b = blockIdx.y;
    {
        float s,c; sincosf(6.2831853071795864769f*(float)tid/256.0f, &s, &c);
        tw[tid] = make_float2(c, s);
    }
    for (int i = tid; i < 32*NM; i += 256){
        int o = i / NM, ky = i % NM;
        float2 v = g_Bf[(((long)b*32 + o)*NM + ky)*S2 + x];
        Bsx[i] = v.x;
        Bsy[i] = v.y;
    }
    for (int i = tid; i < 32*CP; i += 256){
        int o = i / CP, c = i % CP;
        cws[i] = (c < CIN) ? cw[o*CIN + c] : 0.0f;
    }
    if (tid < 32) cbs[tid] = cb[tid];
    __syncthreads();
    int y = tid;
    float2 ctp[12], stp[12];
#pragma unroll
    for (int jj = 0; jj < 12; jj++){
        int j0 = 2*jj, j1 = 2*jj+1;
        int k0 = (j0 < 12) ? j0 : j0 + 105;
        int k1 = (j1 < 12) ? j1 : j1 + 105;
        float2 w0 = tw[(k0*y)&255];
        float2 w1 = tw[(k1*y)&255];
        ctp[jj] = make_float2(w0.x, w1.x);
        stp[jj] = make_float2(w0.y, w1.y);
    }
    float2 hp[NPAIR];
#pragma unroll
    for (int cc = 0; cc < NPAIR; cc++){
        int c0 = 2*cc, c1 = 2*cc+1;
        float h0 = hin[(((long)b*CIN + c0)*S2 + x)*S2 + y];
        float h1 = (c1 < CIN) ? hin[(((long)b*CIN + c1)*S2 + x)*S2 + y] : 0.0f;
        hp[cc] = make_float2(h0, h1);
    }
    for (int o = 0; o < 32; o++){
        float2 accc = make_float2(0.f,0.f);
#pragma unroll
        for (int cc = 0; cc < NPAIR; cc++)
            accc = ffma2(hp[cc], *(const float2*)&cws[o*CP + 2*cc], accc);
        float2 acc_ct = make_float2(0.f,0.f), acc_st = make_float2(0.f,0.f);
#pragma unroll
        for (int jj = 0; jj < 12; jj++){
            acc_ct = ffma2(ctp[jj], *(const float2*)&Bsx[o*NM + 2*jj], acc_ct);
            acc_st = ffma2(stp[jj], *(const float2*)&Bsy[o*NM + 2*jj], acc_st);
        }
        float acc = cbs[o] + accc.x + accc.y
                  + (acc_ct.x + acc_ct.y) - (acc_st.x + acc_st.y);
        float val = last ? acc : gelu_exact(acc);
        hout[(((long)b*32 + o)*S2 + x)*S2 + y] = val;
        rowbuf[o*RP + y] = val;
    }
    if (!last){
        __syncthreads();
        row_dft_emit(rowbuf, tw, 32, 32, b, x, tid);
    }
}

// ---------------- final: fc1 + gelu + fc2 ----------------
__global__ void __launch_bounds__(128) k_final(int flip, const float* __restrict__ w1,
                                               const float* __restrict__ b1,
                                               const float* __restrict__ w2,
                                               const float* __restrict__ b2,
                                               float* __restrict__ out){
    const float* hin = flip ? g_hB : g_hA;
    __shared__ __align__(8) float w1t[128*32];   // transposed: [j][c]
    __shared__ float b1s[128];
    __shared__ float w2s[128];
    int tid = threadIdx.x;
    int x = blockIdx.x, b = blockIdx.y;
    for (int i = tid; i < 4096; i += 128){
        int c = i >> 7, j = i & 127;
        w1t[j*32 + c] = w1[i];
    }
    if (tid < 128){ b1s[tid] = b1[tid]; w2s[tid] = w2[tid]; }
    __syncthreads();
    float bias2 = b2[0];
    float2 hpa[16], hpb[16];
#pragma unroll
    for (int cc = 0; cc < 16; cc++){
        long b0 = (((long)b*32 + 2*cc  )*S2 + x)*S2;
        long b1i = (((long)b*32 + 2*cc+1)*S2 + x)*S2;
        hpa[cc] = make_float2(hin[b0 + tid],       hin[b1i + tid]);
        hpb[cc] = make_float2(hin[b0 + tid + 128], hin[b1i + tid + 128]);
    }
    float acca = bias2, accb = bias2;
    for (int j = 0; j < 128; j++){
        float2 ta2 = make_float2(0.f,0.f), tb2 = make_float2(0.f,0.f);
#pragma unroll
        for (int cc = 0; cc < 16; cc++){
            float2 w2v = *(const float2*)&w1t[j*32 + 2*cc];
            ta2 = ffma2(hpa[cc], w2v, ta2);
            tb2 = ffma2(hpb[cc], w2v, tb2);
        }
        float ta = b1s[j] + ta2.x + ta2.y;
        float tb = b1s[j] + tb2.x + tb2.y;
        float wj = w2s[j];
        acca += gelu_exact(ta)*wj;
        accb += gelu_exact(tb)*wj;
    }
    long ob = ((long)(b*S2 + x))*S2;
    out[ob + tid]       = acca;
    out[ob + tid + 128] = accb;
}

extern "C" void kernel_launch(void* const* d_in, const int* in_sizes, int n_in,
                              void* d_out, int out_size){
    (void)in_sizes; (void)n_in; (void)out_size;
    const float* x    = (const float*)d_in[0];
    const float* ap   = (const float*)d_in[1];
    const float* fc0w = (const float*)d_in[2];
    const float* fc0b = (const float*)d_in[3];
    const float* rbw[4] = {(const float*)d_in[4],(const float*)d_in[5],
                           (const float*)d_in[6],(const float*)d_in[7]};
    const float* cw[4]  = {(const float*)d_in[8],(const float*)d_in[10],
                           (const float*)d_in[12],(const float*)d_in[14]};
    const float* cb[4]  = {(const float*)d_in[9],(const float*)d_in[11],
                           (const float*)d_in[13],(const float*)d_in[15]};
    const float* fc1w = (const float*)d_in[16];
    const float* fc1b = (const float*)d_in[17];
    const float* fc2w = (const float*)d_in[18];
    const float* fc2b = (const float*)d_in[19];
    float* out = (float*)d_out;

    k_front<<<dim3(S2, NB), 256>>>(x, ap, fc0w, fc0b);   // also emits y-DFT (33 ch)
    int flip = 0;
    for (int blk = 0; blk < 4; blk++){
        int Cin = (blk == 0) ? 33 : 32;
        size_t smul_smem = (size_t)(Cin*32 + NB*Cin) * sizeof(float2);
        k_dftx<<<NB*Cin, 576>>>();
        k_smul2<<<NM*NM, 256, smul_smem>>>(rbw[blk], Cin);
        k_invx<<<dim3(32, NB), 256>>>();
        if (blk == 0) k_fuse<33><<<dim3(S2, NB), 256>>>(flip, cw[blk], cb[blk], 0);
        else          k_fuse<32><<<dim3(S2, NB), 256>>>(flip, cw[blk], cb[blk], blk == 3);
        flip ^= 1;
    }
    k_final<<<dim3(S2, NB), 128>>>(flip, fc1w, fc1b, fc2w, fc2b, out);
}

// round 6
// speedup vs baseline: 1.7347x; 1.7347x over previous
#include <cuda_runtime.h>
#include <math.h>

#define S2 256
#define NB 8
#define NM 24
#define RP 260   // padded row pitch (floats): 16B-aligned rows, conflict-free LDS128

__device__ float  g_hA[NB*33*S2*S2];
__device__ float  g_hB[NB*33*S2*S2];
__device__ float2 g_A [NB*S2*33*NM];   // layout [b][x][c][kyi]
__device__ float2 g_Xf[NB*33*NM*NM];
__device__ float2 g_Yf[NB*32*NM*NM];
__device__ float2 g_Bf[NB*32*NM*S2];

__device__ __forceinline__ float gelu_exact(float v){
    return 0.5f*v*(1.0f + erff(v*0.7071067811865475f));
}

// packed dual-FMA: (a.x*b.x+c.x, a.y*b.y+c.y) in one FFMA2
__device__ __forceinline__ float2 ffma2(float2 a, float2 b, float2 c){
    float2 d;
    unsigned long long ra = *reinterpret_cast<unsigned long long*>(&a);
    unsigned long long rb = *reinterpret_cast<unsigned long long*>(&b);
    unsigned long long rc = *reinterpret_cast<unsigned long long*>(&c);
    unsigned long long rd;
    asm("fma.rn.f32x2 %0, %1, %2, %3;" : "=l"(rd) : "l"(ra), "l"(rb), "l"(rc));
    *reinterpret_cast<unsigned long long*>(&d) = rd;
    return d;
}

// row DFT: rowbuf[c][y] -> sA[c*NM+kyi] (acc = (re, im)); twn[i] = (cos, -sin).
// k-major mapping: warp-uniform twiddle broadcast, conflict-free h reads.
__device__ __forceinline__ void row_dft_to_smem(const float* rowbuf, const float2* twn,
                                                float2* sA, int C, int tid){
    int lane = tid & 31, warp = tid >> 5;
#pragma unroll
    for (int rep = 0; rep < 3; rep++){
        int kyi = warp + 8*rep;
        int k = (kyi < 12) ? kyi : kyi + 105;
        const float4* rp4 = reinterpret_cast<const float4*>(rowbuf + lane*RP);
        float2 a0 = make_float2(0.f,0.f), a1 = a0, a2 = a0, a3 = a0;
        int idx = 0;
#pragma unroll 4
        for (int g = 0; g < 64; g++){
            float4 h4 = rp4[g];
            a0 = ffma2(make_float2(h4.x,h4.x), twn[ idx        & 255], a0);
            a1 = ffma2(make_float2(h4.y,h4.y), twn[(idx+k)     & 255], a1);
            a2 = ffma2(make_float2(h4.z,h4.z), twn[(idx+2*k)   & 255], a2);
            a3 = ffma2(make_float2(h4.w,h4.w), twn[(idx+3*k)   & 255], a3);
            idx += 4*k;
        }
        sA[lane*NM + kyi] = make_float2(a0.x+a1.x+a2.x+a3.x, a0.y+a1.y+a2.y+a3.y);
    }
    if (C > 32 && tid < NM){   // tail channel c=32
        int kyi = tid;
        int k = (kyi < 12) ? kyi : kyi + 105;
        const float4* rp4 = reinterpret_cast<const float4*>(rowbuf + 32*RP);
        float2 acc = make_float2(0.f,0.f);
        int idx = 0;
        for (int g = 0; g < 64; g++){
            float4 h4 = rp4[g];
            acc = ffma2(make_float2(h4.x,h4.x), twn[ idx      & 255], acc);
            acc = ffma2(make_float2(h4.y,h4.y), twn[(idx+k)   & 255], acc);
            acc = ffma2(make_float2(h4.z,h4.z), twn[(idx+2*k) & 255], acc);
            acc = ffma2(make_float2(h4.w,h4.w), twn[(idx+3*k) & 255], acc);
            idx += 4*k;
        }
        sA[32*NM + kyi] = acc;
    }
}

// ------- front: fc0 + grid feats + concat a + h*a (NCHW, 33 ch) + fused y-DFT ----
__global__ void __launch_bounds__(256) k_front(const float* __restrict__ x,
                        const float* __restrict__ ap,
                        const float* __restrict__ fw, const float* __restrict__ fb){
    __shared__ __align__(16) float ws[12*32];
    __shared__ __align__(8)  float bs[32];
    __shared__ float2 twn[256];
    __shared__ __align__(16) float rowbuf[33*RP];
    __shared__ float2 sA[33*NM];
    int tid = threadIdx.x;
    for (int i = tid; i < 384; i += 256) ws[i] = fw[i];
    if (tid < 32) bs[tid] = fb[tid];
    {
        float s,c; sincosf(6.2831853071795864769f*(float)tid/256.0f, &s, &c);
        twn[tid] = make_float2(c, -s);
    }
    __syncthreads();
    int xi = blockIdx.x, b = blockIdx.y;
    int y = tid;
    int pix = (b*S2 + xi)*S2 + y;
    const float* xp = x + (long)pix*10;
    float2 featp[12];
#pragma unroll
    for (int t=0;t<10;t++){ float f = xp[t]; featp[t] = make_float2(f,f); }
    { float f = xi*(1.0f/255.0f); featp[10] = make_float2(f,f); }
    { float f = y *(1.0f/255.0f); featp[11] = make_float2(f,f); }
    float av = ap[pix];
    float2 accp[16];
#pragma unroll
    for (int cc=0; cc<16; cc++) accp[cc] = *(const float2*)&bs[2*cc];
#pragma unroll
    for (int t=0; t<12; t++){
        const float4* wst = reinterpret_cast<const float4*>(&ws[t*32]);
#pragma unroll
        for (int q=0; q<8; q++){
            float4 w = wst[q];
            accp[2*q  ] = ffma2(featp[t], make_float2(w.x,w.y), accp[2*q  ]);
            accp[2*q+1] = ffma2(featp[t], make_float2(w.z,w.w), accp[2*q+1]);
        }
    }
    int base = ((b*33)*S2 + xi)*S2 + y;
#pragma unroll
    for (int cc=0; cc<16; cc++){
        float v0 = accp[cc].x*av, v1 = accp[cc].y*av;
        g_hA[base + (2*cc  )*S2*S2] = v0;
        g_hA[base + (2*cc+1)*S2*S2] = v1;
        rowbuf[(2*cc  )*RP + y] = v0;
        rowbuf[(2*cc+1)*RP + y] = v1;
    }
    float a2 = av*av;
    g_hA[base + 32*S2*S2] = a2;
    rowbuf[32*RP + y] = a2;
    __syncthreads();
    row_dft_to_smem(rowbuf, twn, sA, 33, tid);
    __syncthreads();
    long abase = ((long)(b*S2 + xi))*33*NM;
    for (int i = tid; i < 33*NM; i += 256) g_A[abase + i] = sA[i];
}

// ---------------- forward DFT along x at 24 modes (complex) ----------------
__global__ void k_dftx(int Cin){
    __shared__ float2 twx[256];   // (cos, cos)
    __shared__ float2 twy[256];   // (sin, sin)
    __shared__ float2 As[64*NM];
    int tid = threadIdx.x; // 576 threads
    if (tid < 256){
        float s,c; sincosf(6.2831853071795864769f*(float)tid/256.0f, &s, &c);
        twx[tid] = make_float2(c, c);
        twy[tid] = make_float2(s, s);
    }
    int bc = blockIdx.x;
    int b = bc / Cin, cch = bc % Cin;
    int kx = tid / NM, ky = tid % NM;
    int kv = (kx < 12) ? kx : kx + 232;
    float2 acc1 = make_float2(0.f,0.f), acc2 = make_float2(0.f,0.f);
    for (int ch = 0; ch < 4; ch++){
        __syncthreads();
        for (int i = tid; i < 64*NM; i += 576){
            int xr = i / NM, kk = i - xr*NM;
            As[i] = g_A[((long)(b*S2 + ch*64 + xr)*Cin + cch)*NM + kk];
        }
        __syncthreads();
#pragma unroll 4
        for (int xr = 0; xr < 64; xr++){
            int xx = ch*64 + xr;
            float2 av = As[xr*NM + ky];
            int ti = (kv*xx)&255;
            acc1 = ffma2(av, twx[ti], acc1);
            acc2 = ffma2(av, twy[ti], acc2);
        }
    }
    // re = sum ax*c + ay*s ; im = sum ay*c - ax*s
    g_Xf[(long)bc*NM*NM + tid] = make_float2(acc1.x + acc2.y, acc1.y - acc2.x);
}

// ------- spectral multiply: one block per mode site, all 8 batches ----------
__global__ void __launch_bounds__(256) k_smul2(const float* __restrict__ rbw, int Cin){
    extern __shared__ float2 sh[];         // Ws[Cin*32] then Xs[8*Cin]
    float2* Ws = sh;
    float2* Xs = sh + Cin*32;
    int site = blockIdx.x;                 // 0..575 = kx*24+ky
    int kx = site / NM, ky = site % NM;
    int corner = (kx >= 12 ? 1 : 0) + (ky >= 12 ? 2 : 0);
    int m1 = (kx >= 12) ? kx - 12 : kx;
    int m2 = (ky >= 12) ? ky - 12 : ky;
    const float* wbase = rbw + ((long)corner*Cin*32*144 + m1*12 + m2)*2;
    int tid = threadIdx.x;
    for (int i = tid; i < Cin*32; i += 256){
        const float* p = wbase + (long)i*288;   // i = c*32 + o
        Ws[i] = make_float2(p[0], p[1]);
    }
    for (int i = tid; i < NB*Cin; i += 256){
        int b = i / Cin, c = i % Cin;
        Xs[i] = g_Xf[((long)(b*Cin + c))*NM*NM + site];
    }
    __syncthreads();
    int b = tid >> 5, o = tid & 31;
    float yr = 0.0f, yi = 0.0f;
    const float2* xrow = Xs + b*Cin;
    for (int c = 0; c < Cin; c++){
        float2 xv = xrow[c];
        float2 wv = Ws[c*32 + o];
        yr += xv.x*wv.x - xv.y*wv.y;
        yi += xv.x*wv.y + xv.y*wv.x;
    }
    g_Yf[((long)(b*32 + o))*NM*NM + site] = make_float2(yr, yi);
}

// ------- inverse DFT along x (24 modes -> 256), alpha/N^2 folded ------
__global__ void k_invx(){
    __shared__ float2 twx[256];   // (cos, cos)
    __shared__ float2 twy[256];   // (sin, sin)
    __shared__ float2 Ys[NM*NM];
    int tid = threadIdx.x;
    int o = blockIdx.x, b = blockIdx.y;
    {
        float s,c; sincosf(6.2831853071795864769f*(float)tid/256.0f, &s, &c);
        twx[tid] = make_float2(c, c);
        twy[tid] = make_float2(s, s);
    }
    for (int i = tid; i < NM*NM; i += 256)
        Ys[i] = g_Yf[((long)b*32 + o)*NM*NM + i];
    __syncthreads();
    int x = tid;
    for (int kyi = 0; kyi < NM; kyi++){
        float2 acc1 = make_float2(0.f,0.f), acc2 = make_float2(0.f,0.f);
#pragma unroll
        for (int kxi = 0; kxi < NM; kxi++){
            int kv = (kxi < 12) ? kxi : kxi + 232;
            float2 yv = Ys[kxi*NM + kyi];
            int ti = (kv*x)&255;
            acc1 = ffma2(yv, twx[ti], acc1);
            acc2 = ffma2(yv, twy[ti], acc2);
        }
        // re = yx*c - yy*s ; im = yx*s + yy*c
        float re = acc1.x - acc2.y;
        float im = acc2.x + acc1.y;
        int kyv = (kyi < 12) ? kyi : kyi + 105;
        float sc = (kyv == 0 || kyv == 128) ? (1.0f/65536.0f) : (2.0f/65536.0f);
        g_Bf[(((long)b*32 + o)*NM + kyi)*S2 + x] = make_float2(re*sc, im*sc);
    }
}

// ------- fused: inv-y DFT (Re) + 1x1 conv + bias + gelu + next-layer y-DFT -------
template<int CIN>
__global__ void __launch_bounds__(256) k_fuse(int flip, const float* __restrict__ cw,
                                              const float* __restrict__ cb, int last){
    const float* hin  = flip ? g_hB : g_hA;
    float*       hout = flip ? g_hA : g_hB;
    constexpr int CP4 = (CIN + 3) & ~3;     // padded channel pitch (mult of 4)
    constexpr int NPAIR = CP4/2;
    __shared__ float2 twn[256];             // (cos, -sin)
    __shared__ __align__(16) float Bsx[32*NM];
    __shared__ __align__(16) float Bsy[32*NM];
    __shared__ __align__(16) float cws[32*CP4];
    __shared__ float  cbs[32];
    __shared__ __align__(16) float rowbuf[32*RP];
    __shared__ float2 sA[32*NM];
    int tid = threadIdx.x;
    int x = blockIdx.x, b = blockIdx.y;
    {
        float s,c; sincosf(6.2831853071795864769f*(float)tid/256.0f, &s, &c);
        twn[tid] = make_float2(c, -s);
    }
    for (int i = tid; i < 32*NM; i += 256){
        int o = i / NM, ky = i % NM;
        float2 v = g_Bf[(((long)b*32 + o)*NM + ky)*S2 + x];
        Bsx[i] = v.x;
        Bsy[i] = v.y;
    }
    for (int i = tid; i < 32*CP4; i += 256){
        int o = i / CP4, c = i % CP4;
        cws[i] = (c < CIN) ? cw[o*CIN + c] : 0.0f;
    }
    if (tid < 32) cbs[tid] = cb[tid];
    __syncthreads();
    int y = tid;
    float2 ctp[12], stp[12];                // stp holds -sin pairs
#pragma unroll
    for (int jj = 0; jj < 12; jj++){
        int j0 = 2*jj, j1 = 2*jj+1;
        int k0 = (j0 < 12) ? j0 : j0 + 105;
        int k1 = (j1 < 12) ? j1 : j1 + 105;
        float2 w0 = twn[(k0*y)&255];
        float2 w1 = twn[(k1*y)&255];
        ctp[jj] = make_float2(w0.x, w1.x);
        stp[jj] = make_float2(w0.y, w1.y);
    }
    float2 hp[NPAIR];
#pragma unroll
    for (int cc = 0; cc < NPAIR; cc++){
        int c0 = 2*cc, c1 = 2*cc+1;
        float h0 = (c0 < CIN) ? hin[(((long)b*CIN + c0)*S2 + x)*S2 + y] : 0.0f;
        float h1 = (c1 < CIN) ? hin[(((long)b*CIN + c1)*S2 + x)*S2 + y] : 0.0f;
        hp[cc] = make_float2(h0, h1);
    }
    for (int o = 0; o < 32; o++){
        const float4* w4 = reinterpret_cast<const float4*>(&cws[o*CP4]);
        float2 accc = make_float2(0.f,0.f);
#pragma unroll
        for (int q = 0; q < CP4/4; q++){
            float4 w = w4[q];
            accc = ffma2(hp[2*q  ], make_float2(w.x,w.y), accc);
            accc = ffma2(hp[2*q+1], make_float2(w.z,w.w), accc);
        }
        const float4* bx4 = reinterpret_cast<const float4*>(&Bsx[o*NM]);
        const float4* by4 = reinterpret_cast<const float4*>(&Bsy[o*NM]);
        float2 act = make_float2(0.f,0.f), ast = make_float2(0.f,0.f);
#pragma unroll
        for (int q = 0; q < 6; q++){
            float4 bx = bx4[q], by = by4[q];
            act = ffma2(ctp[2*q  ], make_float2(bx.x,bx.y), act);
            act = ffma2(ctp[2*q+1], make_float2(bx.z,bx.w), act);
            ast = ffma2(stp[2*q  ], make_float2(by.x,by.y), ast);
            ast = ffma2(stp[2*q+1], make_float2(by.z,by.w), ast);
        }
        float acc = cbs[o] + accc.x + accc.y + act.x + act.y + ast.x + ast.y;
        float val = last ? acc : gelu_exact(acc);
        hout[(((long)b*32 + o)*S2 + x)*S2 + y] = val;
        rowbuf[o*RP + y] = val;
    }
    if (!last){
        __syncthreads();
        row_dft_to_smem(rowbuf, twn, sA, 32, tid);
        __syncthreads();
        long abase = ((long)(b*S2 + x))*32*NM;
        for (int i = tid; i < 32*NM; i += 256) g_A[abase + i] = sA[i];
    }
}

// ---------------- final: fc1 + gelu + fc2 ----------------
__global__ void __launch_bounds__(128) k_final(int flip, const float* __restrict__ w1,
                                               const float* __restrict__ b1,
                                               const float* __restrict__ w2,
                                               const float* __restrict__ b2,
                                               float* __restrict__ out){
    const float* hin = flip ? g_hB : g_hA;
    __shared__ __align__(16) float w1t[128*32];   // transposed: [j][c]
    __shared__ float b1s[128];
    __shared__ float w2s[128];
    int tid = threadIdx.x;
    int x = blockIdx.x, b = blockIdx.y;
    for (int i = tid; i < 4096; i += 128){
        int c = i >> 7, j = i & 127;
        w1t[j*32 + c] = w1[i];
    }
    if (tid < 128){ b1s[tid] = b1[tid]; w2s[tid] = w2[tid]; }
    __syncthreads();
    float bias2 = b2[0];
    float2 hpa[16], hpb[16];
#pragma unroll
    for (int cc = 0; cc < 16; cc++){
        long b0 = (((long)b*32 + 2*cc  )*S2 + x)*S2;
        long b1i = (((long)b*32 + 2*cc+1)*S2 + x)*S2;
        hpa[cc] = make_float2(hin[b0 + tid],       hin[b1i + tid]);
        hpb[cc] = make_float2(hin[b0 + tid + 128], hin[b1i + tid + 128]);
    }
    float acca = bias2, accb = bias2;
    for (int j = 0; j < 128; j++){
        const float4* wj4 = reinterpret_cast<const float4*>(&w1t[j*32]);
        float2 ta2 = make_float2(0.f,0.f), tb2 = make_float2(0.f,0.f);
#pragma unroll
        for (int q = 0; q < 8; q++){
            float4 w = wj4[q];
            float2 wlo = make_float2(w.x,w.y), whi = make_float2(w.z,w.w);
            ta2 = ffma2(hpa[2*q  ], wlo, ta2);
            ta2 = ffma2(hpa[2*q+1], whi, ta2);
            tb2 = ffma2(hpb[2*q  ], wlo, tb2);
            tb2 = ffma2(hpb[2*q+1], whi, tb2);
        }
        float ta = b1s[j] + ta2.x + ta2.y;
        float tb = b1s[j] + tb2.x + tb2.y;
        float wj = w2s[j];
        acca += gelu_exact(ta)*wj;
        accb += gelu_exact(tb)*wj;
    }
    long ob = ((long)(b*S2 + x))*S2;
    out[ob + tid]       = acca;
    out[ob + tid + 128] = accb;
}

extern "C" void kernel_launch(void* const* d_in, const int* in_sizes, int n_in,
                              void* d_out, int out_size){
    (void)in_sizes; (void)n_in; (void)out_size;
    const float* x    = (const float*)d_in[0];
    const float* ap   = (const float*)d_in[1];
    const float* fc0w = (const float*)d_in[2];
    const float* fc0b = (const float*)d_in[3];
    const float* rbw[4] = {(const float*)d_in[4],(const float*)d_in[5],
                           (const float*)d_in[6],(const float*)d_in[7]};
    const float* cw[4]  = {(const float*)d_in[8],(const float*)d_in[10],
                           (const float*)d_in[12],(const float*)d_in[14]};
    const float* cb[4]  = {(const float*)d_in[9],(const float*)d_in[11],
                           (const float*)d_in[13],(const float*)d_in[15]};
    const float* fc1w = (const float*)d_in[16];
    const float* fc1b = (const float*)d_in[17];
    const float* fc2w = (const float*)d_in[18];
    const float* fc2b = (const float*)d_in[19];
    float* out = (float*)d_out;

    k_front<<<dim3(S2, NB), 256>>>(x, ap, fc0w, fc0b);   // also emits y-DFT (33 ch)
    int flip = 0;
    for (int blk = 0; blk < 4; blk++){
        int Cin = (blk == 0) ? 33 : 32;
        size_t smul_smem = (size_t)(Cin*32 + NB*Cin) * sizeof(float2);
        k_dftx<<<NB*Cin, 576>>>(Cin);
        k_smul2<<<NM*NM, 256, smul_smem>>>(rbw[blk], Cin);
        k_invx<<<dim3(32, NB), 256>>>();
        if (blk == 0) k_fuse<33><<<dim3(S2, NB), 256>>>(flip, cw[blk], cb[blk], 0);
        else          k_fuse<32><<<dim3(S2, NB), 256>>>(flip, cw[blk], cb[blk], blk == 3);
        flip ^= 1;
    }
    k_final<<<dim3(S2, NB), 128>>>(flip, fc1w, fc1b, fc2w, fc2b, out);
}

// round 13
// speedup vs baseline: 1.9622x; 1.1311x over previous
#include <cuda_runtime.h>
#include <math.h>

#define S2 256
#define NB 8
#define NM 24
#define RP 260   // padded row pitch (floats): 16B-aligned rows, conflict-free LDS128

__device__ float  g_hA[NB*33*S2*S2];
__device__ float  g_hB[NB*33*S2*S2];
__device__ float2 g_A [NB*S2*33*NM];   // layout [b][x][c][kyi]
__device__ float2 g_Xf[NB*33*NM*NM];
__device__ float2 g_Yf[NB*32*NM*NM];
__device__ float2 g_Bf[NB*32*NM*S2];

__device__ __forceinline__ float gelu_exact(float v){
    return 0.5f*v*(1.0f + erff(v*0.7071067811865475f));
}

__device__ __forceinline__ float2 ffma2(float2 a, float2 b, float2 c){
    float2 d;
    unsigned long long ra = *reinterpret_cast<unsigned long long*>(&a);
    unsigned long long rb = *reinterpret_cast<unsigned long long*>(&b);
    unsigned long long rc = *reinterpret_cast<unsigned long long*>(&c);
    unsigned long long rd;
    asm("fma.rn.f32x2 %0, %1, %2, %3;" : "=l"(rd) : "l"(ra), "l"(rb), "l"(rc));
    *reinterpret_cast<unsigned long long*>(&d) = rd;
    return d;
}

// slot maps: slots 0..11 = even-k modes, 12..23 = odd-k modes
__device__ __forceinline__ int slot_j(int s){   // slot -> kyi index (0..23)
    if (s < 6)  return 2*s;
    if (s < 12) return 13 + 2*(s-6);
    if (s < 18) return 1 + 2*(s-12);
    return 12 + 2*(s-18);
}
__device__ __forceinline__ int slot_k(int s){   // slot -> actual frequency k
    if (s < 6)  return 2*s;
    if (s < 12) return 118 + 2*(s-6);
    if (s < 18) return 1 + 2*(s-12);
    return 117 + 2*(s-18);
}

// halved row DFT (after butterfly): rowbuf[c][0..127]=h+, [c][128..255]=h-
__device__ __forceinline__ void row_dft_emit_half(const float* rowbuf, const float2* twn,
                                                  int Cin, int b, int x, int tid, int nwarp){
    int lane = tid & 31, warp = tid >> 5;
    long abase = ((long)(b*S2 + x))*Cin*NM;
    for (int kyi = warp; kyi < NM; kyi += nwarp){
        int k = (kyi < 12) ? kyi : kyi + 105;
        const float4* rp4 = reinterpret_cast<const float4*>(rowbuf + lane*RP + ((k&1)?128:0));
        float2 a0 = make_float2(0.f,0.f), a1 = a0, a2 = a0, a3 = a0;
        int idx = 0;
#pragma unroll 4
        for (int g = 0; g < 32; g++){
            float4 h4 = rp4[g];
            a0 = ffma2(make_float2(h4.x,h4.x), twn[ idx        & 255], a0);
            a1 = ffma2(make_float2(h4.y,h4.y), twn[(idx+k)     & 255], a1);
            a2 = ffma2(make_float2(h4.z,h4.z), twn[(idx+2*k)   & 255], a2);
            a3 = ffma2(make_float2(h4.w,h4.w), twn[(idx+3*k)   & 255], a3);
            idx += 4*k;
        }
        g_A[abase + lane*NM + kyi] = make_float2(a0.x+a1.x+a2.x+a3.x, a0.y+a1.y+a2.y+a3.y);
    }
}

// ------- front: fc0 + grid feats + a-mul (NCHW, 33 ch) + butterfly + y-DFT ----
__global__ void __launch_bounds__(256) k_front(const float* __restrict__ x,
                        const float* __restrict__ ap,
                        const float* __restrict__ fw, const float* __restrict__ fb){
    __shared__ __align__(16) float ws[12*32];
    __shared__ __align__(8)  float bs[32];
    __shared__ float2 twn[256];
    __shared__ __align__(16) float rowbuf[33*RP];
    int tid = threadIdx.x;
    for (int i = tid; i < 384; i += 256) ws[i] = fw[i];
    if (tid < 32) bs[tid] = fb[tid];
    {
        float s,c; sincosf(6.2831853071795864769f*(float)tid/256.0f, &s, &c);
        twn[tid] = make_float2(c, -s);
    }
    __syncthreads();
    int xi = blockIdx.x, b = blockIdx.y;
    int y = tid;
    int pix = (b*S2 + xi)*S2 + y;
    const float* xp = x + (long)pix*10;
    float2 featp[12];
#pragma unroll
    for (int t=0;t<10;t++){ float f = xp[t]; featp[t] = make_float2(f,f); }
    { float f = xi*(1.0f/255.0f); featp[10] = make_float2(f,f); }
    { float f = y *(1.0f/255.0f); featp[11] = make_float2(f,f); }
    float av = ap[pix];
    float2 accp[16];
#pragma unroll
    for (int cc=0; cc<16; cc++) accp[cc] = *(const float2*)&bs[2*cc];
#pragma unroll
    for (int t=0; t<12; t++){
        const float4* wst = reinterpret_cast<const float4*>(&ws[t*32]);
#pragma unroll
        for (int q=0; q<8; q++){
            float4 w = wst[q];
            accp[2*q  ] = ffma2(featp[t], make_float2(w.x,w.y), accp[2*q  ]);
            accp[2*q+1] = ffma2(featp[t], make_float2(w.z,w.w), accp[2*q+1]);
        }
    }
    int base = ((b*33)*S2 + xi)*S2 + y;
#pragma unroll
    for (int cc=0; cc<16; cc++){
        float v0 = accp[cc].x*av, v1 = accp[cc].y*av;
        g_hA[base + (2*cc  )*S2*S2] = v0;
        g_hA[base + (2*cc+1)*S2*S2] = v1;
        rowbuf[(2*cc  )*RP + y] = v0;
        rowbuf[(2*cc+1)*RP + y] = v1;
    }
    float a2 = av*av;
    g_hA[base + 32*S2*S2] = a2;
    rowbuf[32*RP + y] = a2;
    __syncthreads();
    for (int i = tid; i < 33*128; i += 256){
        int c = i >> 7, yy = i & 127;
        float a = rowbuf[c*RP + yy], bb = rowbuf[c*RP + yy + 128];
        rowbuf[c*RP + yy] = a + bb;
        rowbuf[c*RP + yy + 128] = a - bb;
    }
    __syncthreads();
    row_dft_emit_half(rowbuf, twn, 33, b, xi, tid, 8);
    if (tid < NM){   // tail channel c=32
        int kyi = tid;
        int k = (kyi < 12) ? kyi : kyi + 105;
        const float4* rp4 = reinterpret_cast<const float4*>(rowbuf + 32*RP + ((k&1)?128:0));
        float2 acc = make_float2(0.f,0.f);
        int idx = 0;
        for (int g = 0; g < 32; g++){
            float4 h4 = rp4[g];
            acc = ffma2(make_float2(h4.x,h4.x), twn[ idx      & 255], acc);
            acc = ffma2(make_float2(h4.y,h4.y), twn[(idx+k)   & 255], acc);
            acc = ffma2(make_float2(h4.z,h4.z), twn[(idx+2*k) & 255], acc);
            acc = ffma2(make_float2(h4.w,h4.w), twn[(idx+3*k) & 255], acc);
            idx += 4*k;
        }
        g_A[((long)(b*S2 + xi))*33*NM + 32*NM + kyi] = acc;
    }
}

// ------- forward DFT along x at 24 modes (complex), radix-2 split ---------
__global__ void k_dftx(int Cin){
    __shared__ float2 twx[256];
    __shared__ float2 twy[256];
    __shared__ float2 Asp[64*NM];
    __shared__ float2 Asm[64*NM];
    int tid = threadIdx.x; // 576 threads
    if (tid < 256){
        float s,c; sincosf(6.2831853071795864769f*(float)tid/256.0f, &s, &c);
        twx[tid] = make_float2(c, c);
        twy[tid] = make_float2(s, s);
    }
    int bc = blockIdx.x;
    int b = bc / Cin, cch = bc % Cin;
    int kx = tid / NM, ky = tid % NM;
    int kv = (kx < 12) ? kx : kx + 232;
    int par = kv & 1;
    float2 acc1 = make_float2(0.f,0.f), acc2 = make_float2(0.f,0.f);
    for (int ch = 0; ch < 2; ch++){
        __syncthreads();
        for (int i = tid; i < 64*NM; i += 576){
            int xr = i / NM, kk = i - xr*NM;
            int xg = ch*64 + xr;
            float2 a  = g_A[((long)(b*S2 + xg      )*Cin + cch)*NM + kk];
            float2 bb = g_A[((long)(b*S2 + xg + 128)*Cin + cch)*NM + kk];
            Asp[i] = make_float2(a.x+bb.x, a.y+bb.y);
            Asm[i] = make_float2(a.x-bb.x, a.y-bb.y);
        }
        __syncthreads();
        const float2* As = par ? Asm : Asp;
#pragma unroll 4
        for (int xr = 0; xr < 64; xr++){
            int xx = ch*64 + xr;
            float2 av = As[xr*NM + ky];
            int ti = (kv*xx)&255;
            acc1 = ffma2(av, twx[ti], acc1);
            acc2 = ffma2(av, twy[ti], acc2);
        }
    }
    g_Xf[(long)bc*NM*NM + tid] = make_float2(acc1.x + acc2.y, acc1.y - acc2.x);
}

// ------- spectral multiply: one block per mode site, all 8 batches ----------
__global__ void __launch_bounds__(256) k_smul2(const float* __restrict__ rbw, int Cin){
    extern __shared__ float2 sh[];
    float2* Ws = sh;
    float2* Xs = sh + Cin*32;
    int site = blockIdx.x;
    int kx = site / NM, ky = site % NM;
    int corner = (kx >= 12 ? 1 : 0) + (ky >= 12 ? 2 : 0);
    int m1 = (kx >= 12) ? kx - 12 : kx;
    int m2 = (ky >= 12) ? ky - 12 : ky;
    const float* wbase = rbw + ((long)corner*Cin*32*144 + m1*12 + m2)*2;
    int tid = threadIdx.x;
    for (int i = tid; i < Cin*32; i += 256){
        const float* p = wbase + (long)i*288;
        Ws[i] = make_float2(p[0], p[1]);
    }
    for (int i = tid; i < NB*Cin; i += 256){
        int b = i / Cin, c = i % Cin;
        Xs[i] = g_Xf[((long)(b*Cin + c))*NM*NM + site];
    }
    __syncthreads();
    int b = tid >> 5, o = tid & 31;
    float yr = 0.0f, yi = 0.0f;
    const float2* xrow = Xs + b*Cin;
    for (int c = 0; c < Cin; c++){
        float2 xv = xrow[c];
        float2 wv = Ws[c*32 + o];
        yr += xv.x*wv.x - xv.y*wv.y;
        yi += xv.x*wv.y + xv.y*wv.x;
    }
    g_Yf[((long)(b*32 + o))*NM*NM + site] = make_float2(yr, yi);
}

// ------- inverse DFT along x: E/O parity split, 2 pixels per thread ---------
__global__ void __launch_bounds__(128) k_invx(){
    __shared__ float2 twx[256];
    __shared__ float2 twy[256];
    __shared__ float2 Ys[NM*NM];
    int tid = threadIdx.x;
    int o = blockIdx.x, b = blockIdx.y;
    for (int i = tid; i < 256; i += 128){
        float s,c; sincosf(6.2831853071795864769f*(float)i/256.0f, &s, &c);
        twx[i] = make_float2(c, c);
        twy[i] = make_float2(s, s);
    }
    for (int i = tid; i < NM*NM; i += 128){
        int slot = i / NM, kyi = i - slot*NM;
        int kxi = (slot < 12) ? 2*slot : 2*(slot-12)+1;
        Ys[i] = g_Yf[((long)b*32 + o)*NM*NM + kxi*NM + kyi];
    }
    __syncthreads();
    int x = tid;
    for (int kyi = 0; kyi < NM; kyi++){
        float2 E1 = make_float2(0.f,0.f), E2 = E1, O1 = E1, O2 = E1;
#pragma unroll
        for (int s = 0; s < 12; s++){
            int kxi = 2*s;
            int kv = (kxi < 12) ? kxi : kxi + 232;
            float2 yv = Ys[s*NM + kyi];
            int ti = (kv*x)&255;
            E1 = ffma2(yv, twx[ti], E1);
            E2 = ffma2(yv, twy[ti], E2);
        }
#pragma unroll
        for (int s = 0; s < 12; s++){
            int kxi = 2*s+1;
            int kv = (kxi < 12) ? kxi : kxi + 232;
            float2 yv = Ys[(s+12)*NM + kyi];
            int ti = (kv*x)&255;
            O1 = ffma2(yv, twx[ti], O1);
            O2 = ffma2(yv, twy[ti], O2);
        }
        float reE = E1.x - E2.y, imE = E2.x + E1.y;
        float reO = O1.x - O2.y, imO = O2.x + O1.y;
        int kyv = (kyi < 12) ? kyi : kyi + 105;
        float sc = (kyv == 0 || kyv == 128) ? (1.0f/65536.0f) : (2.0f/65536.0f);
        long bo = (((long)b*32 + o)*NM + kyi)*S2;
        g_Bf[bo + x]       = make_float2((reE+reO)*sc, (imE+imO)*sc);
        g_Bf[bo + x + 128] = make_float2((reE-reO)*sc, (imE-imO)*sc);
    }
}

// ------- fused: inv-y DFT + 1x1 conv (+gelu +butterfly +y-DFT | +fc1/fc2) ---
// 128 threads, thread t handles pixels y=t and y=t+128 (E/O output pairing).
// LAST: the layer output stays in registers and fc1+gelu+fc2 run in-block;
//       smem pool is re-used for the transposed fc1 weights after the o-loop.
template<int CIN, bool LAST>
__global__ void __launch_bounds__(128) k_fuse(int flip, const float* __restrict__ cw,
                                              const float* __restrict__ cb,
                                              const float* __restrict__ w1,
                                              const float* __restrict__ b1,
                                              const float* __restrict__ w2,
                                              const float* __restrict__ b2,
                                              float* __restrict__ out){
    const float* hin  = flip ? g_hB : g_hA;
    float*       hout = flip ? g_hA : g_hB;
    constexpr int CP4 = (CIN + 3) & ~3;
    constexpr int NPAIR = CP4/2;
    // pool layout (floats): twn[512] | Bsx[768] | Bsy[768] | cws[32*CP4]
    // phase-2 (LAST): w1t[4096] aliases the whole pool
    constexpr int POOL = LAST ? 4096 : (512 + 768 + 768 + 32*CP4);
    __shared__ __align__(16) float pool[POOL];
    float2* twn = reinterpret_cast<float2*>(pool);
    float*  Bsx = pool + 512;
    float*  Bsy = pool + 1280;
    float*  cws = pool + 2048;
    __shared__ float cbs[32];
    __shared__ float b1s[LAST ? 128 : 1];
    __shared__ float w2s[LAST ? 128 : 1];
    __shared__ __align__(16) float rowbuf[LAST ? 1 : 32*RP];
    int tid = threadIdx.x;   // 128
    int x = blockIdx.x, b = blockIdx.y;
    for (int i = tid; i < 256; i += 128){
        float s,c; sincosf(6.2831853071795864769f*(float)i/256.0f, &s, &c);
        twn[i] = make_float2(c, -s);
    }
    for (int i = tid; i < 32*NM; i += 128){
        int o = i / NM, slot = i - o*NM;
        int j = slot_j(slot);
        float2 v = g_Bf[(((long)b*32 + o)*NM + j)*S2 + x];
        Bsx[i] = v.x;
        Bsy[i] = v.y;
    }
    for (int i = tid; i < 32*CP4; i += 128){
        int o = i / CP4, c = i - o*CP4;
        cws[i] = (c < CIN) ? cw[o*CIN + c] : 0.0f;
    }
    if (tid < 32) cbs[tid] = cb[tid];
    __syncthreads();
    int y = tid;   // pixel 0; pixel 1 = y+128
    float2 ctp[12], stp[12];
#pragma unroll
    for (int jj = 0; jj < 12; jj++){
        int k0 = slot_k(2*jj), k1 = slot_k(2*jj+1);
        float2 w0 = twn[(k0*y)&255];
        float2 w1v = twn[(k1*y)&255];
        ctp[jj] = make_float2(w0.x, w1v.x);
        stp[jj] = make_float2(w0.y, w1v.y);
    }
    float2 hp0[NPAIR], hp1[NPAIR];
#pragma unroll
    for (int cc = 0; cc < NPAIR; cc++){
        int c0 = 2*cc, c1 = 2*cc+1;
        long p0 = (((long)b*CIN + c0)*S2 + x)*S2;
        long p1 = (((long)b*CIN + c1)*S2 + x)*S2;
        float a0 = (c0 < CIN) ? hin[p0 + y]       : 0.0f;
        float b0 = (c1 < CIN) ? hin[p1 + y]       : 0.0f;
        float a1 = (c0 < CIN) ? hin[p0 + y + 128] : 0.0f;
        float b1v = (c1 < CIN) ? hin[p1 + y + 128] : 0.0f;
        hp0[cc] = make_float2(a0, b0);
        hp1[cc] = make_float2(a1, b1v);
    }
    float2 hv0[16], hv1[16];   // LAST: layer output pairs (registers)
#pragma unroll
    for (int o = 0; o < 32; o++){
        const float4* w4 = reinterpret_cast<const float4*>(&cws[o*CP4]);
        float2 acc0 = make_float2(0.f,0.f), acc1 = make_float2(0.f,0.f);
#pragma unroll
        for (int q = 0; q < CP4/4; q++){
            float4 w = w4[q];
            float2 wlo = make_float2(w.x,w.y), whi = make_float2(w.z,w.w);
            acc0 = ffma2(hp0[2*q  ], wlo, acc0);
            acc0 = ffma2(hp0[2*q+1], whi, acc0);
            acc1 = ffma2(hp1[2*q  ], wlo, acc1);
            acc1 = ffma2(hp1[2*q+1], whi, acc1);
        }
        const float4* bx4 = reinterpret_cast<const float4*>(&Bsx[o*NM]);
        const float4* by4 = reinterpret_cast<const float4*>(&Bsy[o*NM]);
        float2 actE = make_float2(0.f,0.f), astE = actE, actO = actE, astO = actE;
#pragma unroll
        for (int q = 0; q < 3; q++){
            float4 bx = bx4[q], by = by4[q];
            actE = ffma2(ctp[2*q  ], make_float2(bx.x,bx.y), actE);
            actE = ffma2(ctp[2*q+1], make_float2(bx.z,bx.w), actE);
            astE = ffma2(stp[2*q  ], make_float2(by.x,by.y), astE);
            astE = ffma2(stp[2*q+1], make_float2(by.z,by.w), astE);
        }
#pragma unroll
        for (int q = 3; q < 6; q++){
            float4 bx = bx4[q], by = by4[q];
            actO = ffma2(ctp[2*q  ], make_float2(bx.x,bx.y), actO);
            actO = ffma2(ctp[2*q+1], make_float2(bx.z,bx.w), actO);
            astO = ffma2(stp[2*q  ], make_float2(by.x,by.y), astO);
            astO = ffma2(stp[2*q+1], make_float2(by.z,by.w), astO);
        }
        float E = actE.x + actE.y + astE.x + astE.y;
        float O = actO.x + actO.y + astO.x + astO.y;
        float base = cbs[o];
        float v0 = base + acc0.x + acc0.y + E + O;
        float v1 = base + acc1.x + acc1.y + E - O;
        if (LAST){
            if (o & 1){ hv0[o>>1].y = v0; hv1[o>>1].y = v1; }
            else      { hv0[o>>1].x = v0; hv1[o>>1].x = v1; }
        } else {
            v0 = gelu_exact(v0); v1 = gelu_exact(v1);
            long ho = (((long)b*32 + o)*S2 + x)*S2;
            hout[ho + y]       = v0;
            hout[ho + y + 128] = v1;
            rowbuf[o*RP + y]       = v0;
            rowbuf[o*RP + y + 128] = v1;
        }
    }
    if (LAST){
        // phase 2: fc1 + gelu + fc2 in-block; pool re-used for w1t [j][c]
        __syncthreads();
        float* w1t = pool;
        for (int i = tid; i < 4096; i += 128){
            int c = i >> 7, j = i & 127;
            w1t[j*32 + c] = w1[i];
        }
        b1s[tid] = b1[tid];
        w2s[tid] = w2[tid];
        __syncthreads();
        float bias2 = b2[0];
        float acca = bias2, accb = bias2;
        for (int j = 0; j < 128; j++){
            const float4* wj4 = reinterpret_cast<const float4*>(&w1t[j*32]);
            float2 ta2 = make_float2(0.f,0.f), tb2 = make_float2(0.f,0.f);
#pragma unroll
            for (int q = 0; q < 8; q++){
                float4 w = wj4[q];
                float2 wlo = make_float2(w.x,w.y), whi = make_float2(w.z,w.w);
                ta2 = ffma2(hv0[2*q  ], wlo, ta2);
                ta2 = ffma2(hv0[2*q+1], whi, ta2);
                tb2 = ffma2(hv1[2*q  ], wlo, tb2);
                tb2 = ffma2(hv1[2*q+1], whi, tb2);
            }
            float ta = b1s[j] + ta2.x + ta2.y;
            float tb = b1s[j] + tb2.x + tb2.y;
            float wj = w2s[j];
            acca += gelu_exact(ta)*wj;
            accb += gelu_exact(tb)*wj;
        }
        long ob = ((long)(b*S2 + x))*S2;
        out[ob + y]       = acca;
        out[ob + y + 128] = accb;
    } else {
        __syncthreads();
        for (int i = tid; i < 32*128; i += 128){
            int c = i >> 7, yy = i & 127;
            float a = rowbuf[c*RP + yy], bb = rowbuf[c*RP + yy + 128];
            rowbuf[c*RP + yy] = a + bb;
            rowbuf[c*RP + yy + 128] = a - bb;
        }
        __syncthreads();
        row_dft_emit_half(rowbuf, twn, 32, b, x, tid, 4);
    }
}

extern "C" void kernel_launch(void* const* d_in, const int* in_sizes, int n_in,
                              void* d_out, int out_size){
    (void)in_sizes; (void)n_in; (void)out_size;
    const float* x    = (const float*)d_in[0];
    const float* ap   = (const float*)d_in[1];
    const float* fc0w = (const float*)d_in[2];
    const float* fc0b = (const float*)d_in[3];
    const float* rbw[4] = {(const float*)d_in[4],(const float*)d_in[5],
                           (const float*)d_in[6],(const float*)d_in[7]};
    const float* cw[4]  = {(const float*)d_in[8],(const float*)d_in[10],
                           (const float*)d_in[12],(const float*)d_in[14]};
    const float* cb[4]  = {(const float*)d_in[9],(const float*)d_in[11],
                           (const float*)d_in[13],(const float*)d_in[15]};
    const float* fc1w = (const float*)d_in[16];
    const float* fc1b = (const float*)d_in[17];
    const float* fc2w = (const float*)d_in[18];
    const float* fc2b = (const float*)d_in[19];
    float* out = (float*)d_out;

    k_front<<<dim3(S2, NB), 256>>>(x, ap, fc0w, fc0b);
    int flip = 0;
    for (int blk = 0; blk < 4; blk++){
        int Cin = (blk == 0) ? 33 : 32;
        size_t smul_smem = (size_t)(Cin*32 + NB*Cin) * sizeof(float2);
        k_dftx<<<NB*Cin, 576>>>(Cin);
        k_smul2<<<NM*NM, 256, smul_smem>>>(rbw[blk], Cin);
        k_invx<<<dim3(32, NB), 128>>>();
        if (blk == 0)
            k_fuse<33,false><<<dim3(S2, NB), 128>>>(flip, cw[blk], cb[blk],
                                                    nullptr, nullptr, nullptr, nullptr, nullptr);
        else if (blk < 3)
            k_fuse<32,false><<<dim3(S2, NB), 128>>>(flip, cw[blk], cb[blk],
                                                    nullptr, nullptr, nullptr, nullptr, nullptr);
        else
            k_fuse<32,true ><<<dim3(S2, NB), 128>>>(flip, cw[blk], cb[blk],
                                                    fc1w, fc1b, fc2w, fc2b, out);
        flip ^= 1;
    }
}